// round 10
// baseline (speedup 1.0000x reference)
#include <cuda_runtime.h>

#define NEGV (-9e15f)

constexpr int N  = 512;
constexpr int F  = 64;
constexpr int BS = 8;
constexpr int RWARPS  = 4;            // rows (warps) per CTA
constexpr int THREADS = RWARPS * 32;
constexpr int OUT_OFF = BS * N * F;   // 262144
constexpr float L2E = 1.4426950408889634f;

__device__ __forceinline__ float ex2(float v) {
    float r;
    asm("ex2.approx.f32 %0, %1;" : "=f"(r) : "f"(v));
    return r;
}

__global__ __launch_bounds__(THREADS)
void gat_kernel(const float* __restrict__ x,    // [8,512,1]
                const int*   __restrict__ adj,  // [512,512]
                const float* __restrict__ ext,  // [8,512,8]
                const float* __restrict__ side, // [8,512,1]
                const float* __restrict__ W,    // [1,64]
                const float* __restrict__ a,    // [128,1]
                const float* __restrict__ WS,   // [1,64]
                const float* __restrict__ aS,   // [128,1]
                const float* __restrict__ WQ,   // [2,16]
                const float* __restrict__ WK,   // [2,16]
                const float* __restrict__ WV,   // [1,64]
                float* __restrict__ out)        // [2,8,512,64]
{
    // All 8 scalars pre-scaled by log2(e): every exp is a bare ex2.approx.
    // (leakyrelu commutes with positive scale; sign tests are scale-invariant.)
    __shared__ float  s_c[8];
    __shared__ float4 s_ent[RWARPS][N];   // compacted (s, x_j, j_bits, 0) per row

    const int tid  = threadIdx.x;
    const int lane = tid & 31;
    const int w    = tid >> 5;
    const int row  = blockIdx.x * RWARPS + w;   // b*512 + i
    const int b    = row >> 9;
    const int i    = row & 511;

    // ---- prologue: warp w computes contractions w and w+4 ----
    #pragma unroll
    for (int k = w; k < 8; k += RWARPS) {
        float val;
        if (k < 4) {
            const float* Wp = (k < 2) ? W : WS;
            const float* ap = (k < 2) ? a : aS;
            const int off   = (k & 1) ? 64 : 0;
            val = Wp[lane] * ap[off + lane] + Wp[lane + 32] * ap[off + 32 + lane];
        } else {
            const int l16 = lane & 15;
            const float* q = WQ + (((k == 5) || (k == 7)) ? 16 : 0);
            const float* p = WK + ((k >= 6) ? 16 : 0);
            // 0.5 (dup half-lanes) * 0.25 (1/sqrt(16))
            val = q[l16] * p[l16] * 0.125f;
        }
        #pragma unroll
        for (int o = 16; o; o >>= 1) val += __shfl_xor_sync(0xffffffffu, val, o);
        if (lane == 0) s_c[k] = val * L2E;
    }
    __syncthreads();   // the ONLY cross-warp sync

    const float c1 = s_c[0], c2 = s_c[1], cs1 = s_c[2], cs2 = s_c[3];
    const float A0 = s_c[4], B0 = s_c[5], A1  = s_c[6], B1  = s_c[7];

    const float* xb = x    + (b << 9);
    const float* sb = side + (b << 9);
    const float xi = xb[i];
    const float si = sb[i];
    const float t1 = xi * c1;        // log2 units
    const float t2 = si * cs1;
    const float xiA0 = xi * A0;
    const float xiA1 = xi * A1;

    const float* extb = ext + ((size_t)(b << 9) * 8);
    float ei[8];
    {
        const float4* e4 = (const float4*)(extb + (size_t)i * 8);
        float4 ea = e4[0], eb = e4[1];
        ei[0]=ea.x; ei[1]=ea.y; ei[2]=ea.z; ei[3]=ea.w;
        ei[4]=eb.x; ei[5]=eb.y; ei[6]=eb.z; ei[7]=eb.w;
    }
    const float mean_ei = (ei[0]+ei[1]+ei[2]+ei[3]+ei[4]+ei[5]+ei[6]+ei[7]) * 0.125f;

    // ---- Pass A: vectorized logits, ballot compaction of 16B records ----
    float lmax = NEGV;
    int   cnt  = 0;
    const int4*   ar4 = (const int4*)(adj + (i << 9));
    const float4* xb4 = (const float4*)xb;
    const float4* sb4 = (const float4*)sb;
    #pragma unroll
    for (int blk = 0; blk < 4; blk++) {
        const int j0 = (blk << 7) + (lane << 2);
        int4   av = ar4[(blk << 5) + lane];
        float4 xv = xb4[(blk << 5) + lane];
        float4 sv = sb4[(blk << 5) + lane];
        #pragma unroll
        for (int k = 0; k < 4; k++) {
            float xj = (k==0)?xv.x:(k==1)?xv.y:(k==2)?xv.z:xv.w;
            float sj = (k==0)?sv.x:(k==1)?sv.y:(k==2)?sv.z:sv.w;
            int   ad = (k==0)?av.x:(k==1)?av.y:(k==2)?av.z:av.w;
            float e  = fmaf(c2,  xj, t1);  e  = fmaxf(e,  0.2f * e);  // leakyrelu
            float es = fmaf(cs2, sj, t2);  es = fmaxf(es, 0.2f * es);
            float s  = e + es;             // log2 units
            bool act = (ad > 0) && (s > 0.f);
            unsigned mk = __ballot_sync(0xffffffffu, act);
            if (act) {
                int pos = cnt + __popc(mk & ((1u << lane) - 1u));
                s_ent[w][pos] = make_float4(s, xj, __uint_as_float(j0 + k), 0.f);
                lmax = fmaxf(lmax, s);
            }
            cnt += __popc(mk);
        }
    }
    #pragma unroll
    for (int o = 16; o; o >>= 1)
        lmax = fmaxf(lmax, __shfl_xor_sync(0xffffffffu, lmax, o));
    float m = lmax;

    // Degenerate row (no active j): reference softmax is uniform over ALL 512 j
    // (p = exp(NEG-NEG) = 1). Encode as s=0 entries with m=0 -> p=ex2(0)=1.
    if (cnt == 0) {
        m = 0.f;
        #pragma unroll
        for (int jj = 0; jj < N / 32; jj++) {
            int j = jj * 32 + lane;
            s_ent[w][j] = make_float4(0.f, xb[j], __uint_as_float(j), 0.f);
        }
        cnt = N;
    }

    // ---- Pass B: one LDS.128 per entry, unrolled x2 for MLP ----
    float den = 0.f, ynum = 0.f, znum = 0.f;
    const float4* el = s_ent[w];

    #define PB(TT) {                                                          \
        float4 en = el[TT];                                                   \
        float p  = ex2(en.x - m);                                             \
        float xj = en.y;                                                      \
        unsigned jv = __float_as_uint(en.z);                                  \
        den  += p;                                                            \
        ynum += p * xj;                                                       \
        float qk0 = fmaf(xj, B0, xiA0);                                       \
        float qk1 = fmaf(xj, B1, xiA1);                                       \
        const float4* f4 = (const float4*)(extb + (size_t)jv * 8);            \
        float4 fa = f4[0], fb = f4[1];                                        \
        float s8 = 0.f, wn = 0.f, df, pf;                                     \
        df = fmaf(ei[0], qk0, fa.x * qk1); pf = (df>0.f)?ex2(df):0.f; s8+=pf; wn=fmaf(pf,ei[0],wn); \
        df = fmaf(ei[1], qk0, fa.y * qk1); pf = (df>0.f)?ex2(df):0.f; s8+=pf; wn=fmaf(pf,ei[1],wn); \
        df = fmaf(ei[2], qk0, fa.z * qk1); pf = (df>0.f)?ex2(df):0.f; s8+=pf; wn=fmaf(pf,ei[2],wn); \
        df = fmaf(ei[3], qk0, fa.w * qk1); pf = (df>0.f)?ex2(df):0.f; s8+=pf; wn=fmaf(pf,ei[3],wn); \
        df = fmaf(ei[4], qk0, fb.x * qk1); pf = (df>0.f)?ex2(df):0.f; s8+=pf; wn=fmaf(pf,ei[4],wn); \
        df = fmaf(ei[5], qk0, fb.y * qk1); pf = (df>0.f)?ex2(df):0.f; s8+=pf; wn=fmaf(pf,ei[5],wn); \
        df = fmaf(ei[6], qk0, fb.z * qk1); pf = (df>0.f)?ex2(df):0.f; s8+=pf; wn=fmaf(pf,ei[6],wn); \
        df = fmaf(ei[7], qk0, fb.w * qk1); pf = (df>0.f)?ex2(df):0.f; s8+=pf; wn=fmaf(pf,ei[7],wn); \
        /* all-nonpositive inner row -> reference softmax uniform -> mean(ei) */ \
        znum += p * ((s8 > 0.f) ? __fdividef(wn, s8) : mean_ei);              \
    }

    int t = lane;
    for (; t + 32 < cnt; t += 64) { PB(t) PB(t + 32) }
    if (t < cnt) { PB(t) }
    #undef PB

    #pragma unroll
    for (int o = 16; o; o >>= 1) {
        den  += __shfl_xor_sync(0xffffffffu, den,  o);
        ynum += __shfl_xor_sync(0xffffffffu, ynum, o);
        znum += __shfl_xor_sync(0xffffffffu, znum, o);
    }
    const float y = __fdividef(ynum, den);
    const float z = __fdividef(znum, den);

    // ---- outputs: elu(y*W[f]), elu(z*WV[f]) ----
    size_t base = (size_t)row * F + lane;
    float v;
    v = y * W[lane];        out[base]                = (v > 0.f) ? v : expm1f(v);
    v = y * W[lane + 32];   out[base + 32]           = (v > 0.f) ? v : expm1f(v);
    v = z * WV[lane];       out[OUT_OFF + base]      = (v > 0.f) ? v : expm1f(v);
    v = z * WV[lane + 32];  out[OUT_OFF + base + 32] = (v > 0.f) ? v : expm1f(v);
}

extern "C" void kernel_launch(void* const* d_in, const int* in_sizes, int n_in,
                              void* d_out, int out_size) {
    const float* input = (const float*)d_in[0];
    const int*   adj   = (const int*)  d_in[1];
    const float* ext   = (const float*)d_in[2];
    const float* side  = (const float*)d_in[3];
    const float* W     = (const float*)d_in[4];
    const float* a     = (const float*)d_in[5];
    const float* WS    = (const float*)d_in[6];
    const float* aS    = (const float*)d_in[7];
    const float* WQ    = (const float*)d_in[8];
    const float* WK    = (const float*)d_in[9];
    const float* WV    = (const float*)d_in[10];
    float* out = (float*)d_out;

    gat_kernel<<<(BS * N) / RWARPS, THREADS>>>(input, adj, ext, side,
                                               W, a, WS, aS, WQ, WK, WV, out);
}

// round 11
// speedup vs baseline: 1.2772x; 1.2772x over previous
#include <cuda_runtime.h>

#define NEGV (-9e15f)

constexpr int N  = 512;
constexpr int F  = 64;
constexpr int BS = 8;
constexpr int WARPS = 8;              // 1 warp per row, 8 rows per CTA (same b)
constexpr int THREADS = WARPS * 32;
constexpr int OUT_OFF = BS * N * F;   // 262144
constexpr float L2E = 1.4426950408889634f;

__device__ __forceinline__ float ex2(float v) {
    float r;
    asm("ex2.approx.f32 %0, %1;" : "=f"(r) : "f"(v));
    return r;
}
// elu(v) = v>0 ? v : e^v - 1, via single MUFU (norm-based rel_err tolerates approx)
__device__ __forceinline__ float elu(float v) {
    return (v > 0.f) ? v : (ex2(v * L2E) - 1.f);
}

__global__ __launch_bounds__(THREADS, 4)
void gat_kernel(const float* __restrict__ x,    // [8,512,1]
                const int*   __restrict__ adj,  // [512,512]
                const float* __restrict__ ext,  // [8,512,8]
                const float* __restrict__ side, // [8,512,1]
                const float* __restrict__ W,    // [1,64]
                const float* __restrict__ a,    // [128,1]
                const float* __restrict__ WS,   // [1,64]
                const float* __restrict__ aS,   // [128,1]
                const float* __restrict__ WQ,   // [2,16]
                const float* __restrict__ WK,   // [2,16]
                const float* __restrict__ WV,   // [1,64]
                float* __restrict__ out)        // [2,8,512,64]
{
    // All 8 scalars pre-scaled by log2(e): every exp is a bare ex2.approx.
    __shared__ float  s_c[8];
    __shared__ float4 s_x4 [N / 4];             // x[b]     (2KB)
    __shared__ float4 s_sd4[N / 4];             // side[b]  (2KB)
    __shared__ float4 s_e4 [N * 2];             // ext[b]   (16KB)
    __shared__ float          s_s [WARPS][N];   // compacted logits (16KB)
    __shared__ unsigned short s_jo[WARPS][N];   // compacted j      (8KB)

    const int tid  = threadIdx.x;
    const int lane = tid & 31;
    const int w    = tid >> 5;
    const int row  = blockIdx.x * WARPS + w;    // b*512 + i (CTA: one batch)
    const int b    = row >> 9;
    const int i    = row & 511;

    // ---- prologue: warp w computes scalar contraction w (scaled by L2E) ----
    {
        float val;
        if (w < 4) {
            const float* Wp = (w < 2) ? W : WS;
            const float* ap = (w < 2) ? a : aS;
            const int off   = (w & 1) ? 64 : 0;
            val = Wp[lane] * ap[off + lane] + Wp[lane + 32] * ap[off + 32 + lane];
        } else {
            const int l16 = lane & 15;
            const float* q = WQ + (((w == 5) || (w == 7)) ? 16 : 0);
            const float* k = WK + ((w >= 6) ? 16 : 0);
            // 0.5 (dup half-lanes) * 0.25 (1/sqrt(16))
            val = q[l16] * k[l16] * 0.125f;
        }
        #pragma unroll
        for (int o = 16; o; o >>= 1) val += __shfl_xor_sync(0xffffffffu, val, o);
        if (lane == 0) s_c[w] = val * L2E;
    }

    // ---- CTA-cooperative staging: x, side, whole ext[b] slab ----
    const float4* xb4 = (const float4*)(x    + (b << 9));
    const float4* sb4 = (const float4*)(side + (b << 9));
    const float4* eb4 = (const float4*)(ext  + ((size_t)(b << 9) * 8));
    if (tid < N / 4) {
        s_x4 [tid] = xb4[tid];
        s_sd4[tid] = sb4[tid];
    }
    #pragma unroll
    for (int idx = tid; idx < N * 2; idx += THREADS)
        s_e4[idx] = eb4[idx];
    __syncthreads();   // the ONLY cross-warp sync

    const float c1 = s_c[0], c2 = s_c[1], cs1 = s_c[2], cs2 = s_c[3];
    const float A0 = s_c[4], B0 = s_c[5], A1  = s_c[6], B1  = s_c[7];

    const float* sx = (const float*)s_x4;
    const float* sd = (const float*)s_sd4;
    const float xi = sx[i];
    const float si = sd[i];
    const float t1 = xi * c1;        // log2 units
    const float t2 = si * cs1;
    const float xiA0 = xi * A0;
    const float xiA1 = xi * A1;

    float ei[8];
    {
        float4 ea = s_e4[2 * i], eb = s_e4[2 * i + 1];
        ei[0]=ea.x; ei[1]=ea.y; ei[2]=ea.z; ei[3]=ea.w;
        ei[4]=eb.x; ei[5]=eb.y; ei[6]=eb.z; ei[7]=eb.w;
    }
    const float mean_ei = (ei[0]+ei[1]+ei[2]+ei[3]+ei[4]+ei[5]+ei[6]+ei[7]) * 0.125f;

    // ---- Pass A: vectorized logits (4 j per lane), ballot compaction ----
    float lmax = NEGV;
    int   cnt  = 0;
    const int4* ar4 = (const int4*)(adj + (i << 9));
    #pragma unroll
    for (int blk = 0; blk < 4; blk++) {
        const int j0 = (blk << 7) + (lane << 2);
        int4   av = ar4[(blk << 5) + lane];
        float4 xv = s_x4 [(blk << 5) + lane];
        float4 sv = s_sd4[(blk << 5) + lane];
        #pragma unroll
        for (int k = 0; k < 4; k++) {
            float xj = (k==0)?xv.x:(k==1)?xv.y:(k==2)?xv.z:xv.w;
            float sj = (k==0)?sv.x:(k==1)?sv.y:(k==2)?sv.z:sv.w;
            int   ad = (k==0)?av.x:(k==1)?av.y:(k==2)?av.z:av.w;
            float e  = fmaf(c2,  xj, t1);  e  = fmaxf(e,  0.2f * e);  // leakyrelu
            float es = fmaf(cs2, sj, t2);  es = fmaxf(es, 0.2f * es);
            float s  = e + es;             // log2 units
            bool act = (ad > 0) && (s > 0.f);
            unsigned mk = __ballot_sync(0xffffffffu, act);
            if (act) {
                int pos = cnt + __popc(mk & ((1u << lane) - 1u));
                s_s [w][pos] = s;
                s_jo[w][pos] = (unsigned short)(j0 + k);
                lmax = fmaxf(lmax, s);
            }
            cnt += __popc(mk);
        }
    }
    #pragma unroll
    for (int o = 16; o; o >>= 1)
        lmax = fmaxf(lmax, __shfl_xor_sync(0xffffffffu, lmax, o));
    float m = lmax;

    // Degenerate row (no active j): reference softmax is uniform over ALL 512 j
    // (p = exp(NEG-NEG) = 1). Encode as s=0 entries with m=0 -> p=ex2(0)=1.
    if (cnt == 0) {
        m = 0.f;
        #pragma unroll
        for (int jj = 0; jj < N / 32; jj++) {
            int j = jj * 32 + lane;
            s_s [w][j] = 0.f;
            s_jo[w][j] = (unsigned short)j;
        }
        cnt = N;
    }

    // ---- Pass B: sequential LDS records; ext/x gathers stay in smem ----
    float den = 0.f, ynum = 0.f, znum = 0.f;
    const float*          sls = s_s [w];
    const unsigned short* jls = s_jo[w];
    for (int t = lane; t < cnt; t += 32) {
        float p  = ex2(sls[t] - m);
        int   j  = jls[t];
        float xj = sx[j];                          // smem gather (4B)
        den  += p;
        ynum = fmaf(p, xj, ynum);
        float qk0 = fmaf(xj, B0, xiA0);            // log2-scaled
        float qk1 = fmaf(xj, B1, xiA1);
        float4 fa = s_e4[2 * j];                   // smem gather (16B x2)
        float4 fb = s_e4[2 * j + 1];
        float s8 = 0.f, wn = 0.f, df, pf;
        #define INNER(EIF, EJF) \
            df = fmaf(EIF, qk0, (EJF) * qk1); \
            pf = (df > 0.f) ? ex2(df) : 0.f; \
            s8 += pf;  wn = fmaf(pf, EIF, wn);
        INNER(ei[0], fa.x) INNER(ei[1], fa.y) INNER(ei[2], fa.z) INNER(ei[3], fa.w)
        INNER(ei[4], fb.x) INNER(ei[5], fb.y) INNER(ei[6], fb.z) INNER(ei[7], fb.w)
        #undef INNER
        // all-nonpositive inner row -> reference softmax uniform -> mean(ei)
        znum += p * ((s8 > 0.f) ? __fdividef(wn, s8) : mean_ei);
    }
    #pragma unroll
    for (int o = 16; o; o >>= 1) {
        den  += __shfl_xor_sync(0xffffffffu, den,  o);
        ynum += __shfl_xor_sync(0xffffffffu, ynum, o);
        znum += __shfl_xor_sync(0xffffffffu, znum, o);
    }
    const float y = __fdividef(ynum, den);
    const float z = __fdividef(znum, den);

    // ---- outputs: elu(y*W[f]), elu(z*WV[f]) ----
    size_t base = (size_t)row * F + lane;
    out[base]                = elu(y * W[lane]);
    out[base + 32]           = elu(y * W[lane + 32]);
    out[OUT_OFF + base]      = elu(z * WV[lane]);
    out[OUT_OFF + base + 32] = elu(z * WV[lane + 32]);
}

extern "C" void kernel_launch(void* const* d_in, const int* in_sizes, int n_in,
                              void* d_out, int out_size) {
    const float* input = (const float*)d_in[0];
    const int*   adj   = (const int*)  d_in[1];
    const float* ext   = (const float*)d_in[2];
    const float* side  = (const float*)d_in[3];
    const float* W     = (const float*)d_in[4];
    const float* a     = (const float*)d_in[5];
    const float* WS    = (const float*)d_in[6];
    const float* aS    = (const float*)d_in[7];
    const float* WQ    = (const float*)d_in[8];
    const float* WK    = (const float*)d_in[9];
    const float* WV    = (const float*)d_in[10];
    float* out = (float*)d_out;

    gat_kernel<<<(BS * N) / WARPS, THREADS>>>(input, adj, ext, side,
                                              W, a, WS, aS, WQ, WK, WV, out);
}